// round 10
// baseline (speedup 1.0000x reference)
#include <cuda_runtime.h>
#include <cuda_bf16.h>
#include <cstdint>

#define B_SZ   16
#define SEQ    2048
#define VOCAB  50257
#define EMBED  128
#define DSTATE 16
#define HID    256
#define NCLS   10
#define NEDGE  8192
#define KLEN   64
#define NROW   (B_SZ*SEQ)   // 32768

// ---------------- scratch (static device arrays; no allocation) ----------------
__device__ float g_vproj[VOCAB*DSTATE];    // emb @ B_w^T over vocab   3.2MB
__device__ float g_bmat[B_SZ*DSTATE*SEQ];  // [b][d][t]
__device__ float g_conv[NROW*DSTATE];      // [b][t][d]
__device__ float g_h[NROW*EMBED];          // LN output
__device__ float g_hagg[NROW*EMBED];       // gathered msgs
__device__ float g_w[256*256];             // combined weight [h][k]
__device__ float g_K[DSTATE*KLEN];         // conv taps
__device__ float g_pooled[B_SZ*HID];       // pooled partials
__device__ int   g_cnt[NROW];
__device__ int   g_off[NROW];
__device__ int   g_cur[NROW];
__device__ int   g_srcs[B_SZ*NEDGE];

// ---------------- zero counters / accumulators ----------------
__global__ void k_zero() {
    int i = blockIdx.x * blockDim.x + threadIdx.x;   // 32768
    g_cnt[i] = 0;
    g_cur[i] = 0;
    if (i < B_SZ*HID) g_pooled[i] = 0.f;
}

// ---------------- conv taps ----------------
__global__ void k_prep(const float* __restrict__ A_log) {
    int d = blockIdx.x;
    int tid = threadIdx.x;         // 128
    float a = expf(-expf(A_log[tid*DSTATE + d]));
    float p = 1.f;
    __shared__ float ws[4];
    for (int tau = 0; tau < KLEN; tau++) {
        float s = p;
        for (int o = 16; o; o >>= 1) s += __shfl_down_sync(0xffffffffu, s, o);
        if ((tid & 31) == 0) ws[tid >> 5] = s;
        __syncthreads();
        if (tid == 0) g_K[d*KLEN + tau] = (ws[0]+ws[1]+ws[2]+ws[3]) * (1.f/128.f);
        __syncthreads();
        p *= a;
    }
}

// ---------------- combined weight: g_w[h][k] = [Wupd1 | Wupd2@Wmsg] ----------------
__global__ void k_wcomb(const float* __restrict__ Wupd_w, const float* __restrict__ Wmsg_w) {
    int h = blockIdx.x;     // 256
    int k = threadIdx.x;    // 256
    float v;
    if (k < 128) {
        v = Wupd_w[h*384 + k];
    } else {
        int d = k - 128;
        float acc = 0.f;
        const float* w2 = Wupd_w + h*384 + 128;
        for (int hp = 0; hp < 256; hp++) acc += w2[hp] * Wmsg_w[hp*128 + d];
        v = acc;
    }
    g_w[h*256 + k] = v;
}

// ---------------- vocab projection: vproj[v][d] = emb[v] . B_w[d] ----------------
// Streaming, fully coalesced over the vocab (no gather). Warp per 4 vocab rows;
// lane = (d = lane>>1, kg = lane&1) holds B_w half-row in 16 float4 regs.
__global__ __launch_bounds__(256)
void k_vproj(const float* __restrict__ emb, const float* __restrict__ B_w) {
    int w = (blockIdx.x * blockDim.x + threadIdx.x) >> 5;
    int lane = threadIdx.x & 31;
    int d = lane >> 1, kg = lane & 1;
    float4 wr[16];
    const float4* bw = (const float4*)(B_w + d*EMBED + kg*64);
#pragma unroll
    for (int i = 0; i < 16; i++) wr[i] = bw[i];
    int v0 = w * 4;
#pragma unroll
    for (int j = 0; j < 4; j++) {
        int v = v0 + j;
        if (v >= VOCAB) break;
        const float4* xp = (const float4*)(emb + (size_t)v*EMBED + kg*64);
        float acc = 0.f;
#pragma unroll
        for (int i = 0; i < 16; i++) {
            float4 x = xp[i];
            acc += wr[i].x*x.x + wr[i].y*x.y + wr[i].z*x.z + wr[i].w*x.w;
        }
        acc += __shfl_xor_sync(0xffffffffu, acc, 1);
        if (kg == 0) g_vproj[(size_t)v*DSTATE + d] = acc;
    }
}

// ---------------- token gather + transpose: bmat[b][d][t] = vproj[tok[b][t]][d] ----
#define TSTR 260
__global__ __launch_bounds__(256)
void k_bgather(const int* __restrict__ tokens) {
    __shared__ float st[DSTATE*TSTR];
    int r0 = blockIdx.x * 256;       // 128 blocks; 256 t's within one b
    int b  = r0 >> 11;
    int t0 = r0 & (SEQ-1);
    int t  = threadIdx.x;
    int tok = tokens[r0 + t];
    const float4* vp = (const float4*)(g_vproj + (size_t)tok*DSTATE);
    float4 f0 = vp[0], f1 = vp[1], f2 = vp[2], f3 = vp[3];
    float vals[16] = {f0.x,f0.y,f0.z,f0.w, f1.x,f1.y,f1.z,f1.w,
                      f2.x,f2.y,f2.z,f2.w, f3.x,f3.y,f3.z,f3.w};
#pragma unroll
    for (int d = 0; d < DSTATE; d++) st[d*TSTR + t] = vals[d];
    __syncthreads();
#pragma unroll
    for (int i = t; i < DSTATE*64; i += 256) {
        int d = i >> 6, tq = i & 63;
        *(float4*)(g_bmat + ((size_t)b*DSTATE + d)*SEQ + t0 + tq*4) =
            *(float4*)&st[d*TSTR + tq*4];
    }
}

// ---------------- 64-tap causal convolution (smem-staged) ----------------
__global__ void k_conv() {
    int bd = blockIdx.x;           // 256 = B*DSTATE
    int b = bd >> 4, d = bd & 15;
    __shared__ float sb[SEQ];
    __shared__ float sK[KLEN];
    int tid = threadIdx.x;         // 256
    if (tid < KLEN) sK[tid] = g_K[d*KLEN + tid];
    const float4* bm4 = (const float4*)(g_bmat + bd*SEQ);
    float4* sb4 = (float4*)sb;
    for (int i = tid; i < SEQ/4; i += 256) sb4[i] = bm4[i];
    __syncthreads();
    for (int t0 = tid; t0 < SEQ; t0 += 256) {
        float acc = 0.f;
        int tmax = t0 < (KLEN-1) ? t0 : (KLEN-1);
        for (int tau = 0; tau <= tmax; tau++) acc += sK[tau] * sb[t0 - tau];
        g_conv[(b*SEQ + t0)*DSTATE + d] = acc;
    }
}

// ---------------- y = conv@C^T + D*emb[tok], LayerNorm; warp per row ----------------
__global__ void k_yln(const int* __restrict__ tokens, const float* __restrict__ emb,
                      const float* __restrict__ C_w, const float* __restrict__ Dskip,
                      const float* __restrict__ ln_g, const float* __restrict__ ln_b) {
    int row = blockIdx.x * 8 + (threadIdx.x >> 5);   // 4096 blocks x 8 warps
    int lane = threadIdx.x & 31;
    float cv = 0.f;
    if (lane < DSTATE) cv = g_conv[row*DSTATE + lane];
    float cd[16];
#pragma unroll
    for (int d = 0; d < 16; d++) cd[d] = __shfl_sync(0xffffffffu, cv, d);
    int tok = tokens[row];
    float4 xe = *(const float4*)(emb + (size_t)tok*EMBED + lane*4);
    float4 dk = *(const float4*)(Dskip + lane*4);
    float y[4] = {dk.x*xe.x, dk.y*xe.y, dk.z*xe.z, dk.w*xe.w};
#pragma unroll
    for (int j = 0; j < 4; j++) {
        const float4* cw = (const float4*)(C_w + (lane*4 + j)*DSTATE);
        float4 c0 = cw[0], c1 = cw[1], c2 = cw[2], c3 = cw[3];
        y[j] += cd[0]*c0.x + cd[1]*c0.y + cd[2]*c0.z + cd[3]*c0.w
              + cd[4]*c1.x + cd[5]*c1.y + cd[6]*c1.z + cd[7]*c1.w
              + cd[8]*c2.x + cd[9]*c2.y + cd[10]*c2.z + cd[11]*c2.w
              + cd[12]*c3.x + cd[13]*c3.y + cd[14]*c3.z + cd[15]*c3.w;
    }
    float s  = y[0]+y[1]+y[2]+y[3];
    float s2 = y[0]*y[0]+y[1]*y[1]+y[2]*y[2]+y[3]*y[3];
    for (int o = 16; o; o >>= 1) {
        s  += __shfl_xor_sync(0xffffffffu, s,  o);
        s2 += __shfl_xor_sync(0xffffffffu, s2, o);
    }
    float mu  = s  * (1.f/128.f);
    float var = s2 * (1.f/128.f) - mu*mu;
    float r = rsqrtf(var + 1e-5f);
    float4 lg = *(const float4*)(ln_g + lane*4);
    float4 lb = *(const float4*)(ln_b + lane*4);
    float4 out;
    out.x = lg.x*(y[0]-mu)*r + lb.x;
    out.y = lg.y*(y[1]-mu)*r + lb.y;
    out.z = lg.z*(y[2]-mu)*r + lb.z;
    out.w = lg.w*(y[3]-mu)*r + lb.w;
    *(float4*)(g_h + row*EMBED + lane*4) = out;
}

// ---------------- CSR build ----------------
__global__ void k_count(const int* __restrict__ ei) {
    int idx = blockIdx.x * blockDim.x + threadIdx.x;
    int b = idx >> 13, e = idx & (NEDGE-1);
    int dst = ei[b*2*NEDGE + NEDGE + e];
    atomicAdd(&g_cnt[b*SEQ + dst], 1);
}

__global__ void k_scan() {
    int b = blockIdx.x;
    int tid = threadIdx.x;         // 256
    __shared__ int sp[256];
    int base = b*SEQ + tid*8;
    int c[8];
    int tot = 0;
#pragma unroll
    for (int j = 0; j < 8; j++) { c[j] = g_cnt[base + j]; tot += c[j]; }
    sp[tid] = tot;
    __syncthreads();
    for (int o = 1; o < 256; o <<= 1) {
        int v = (tid >= o) ? sp[tid - o] : 0;
        __syncthreads();
        sp[tid] += v;
        __syncthreads();
    }
    int run = sp[tid] - tot;
#pragma unroll
    for (int j = 0; j < 8; j++) { g_off[base + j] = run; run += c[j]; }
}

__global__ void k_fill(const int* __restrict__ ei) {
    int idx = blockIdx.x * blockDim.x + threadIdx.x;
    int b = idx >> 13, e = idx & (NEDGE-1);
    const int* eb = ei + b*2*NEDGE;
    int src = eb[e];
    int dst = eb[NEDGE + e];
    int node = b*SEQ + dst;
    int pos = g_off[node] + atomicAdd(&g_cur[node], 1);
    g_srcs[b*NEDGE + pos] = src;
}

// ---------------- gather ----------------
__global__ void k_gather() {
    int node = blockIdx.x * 8 + (threadIdx.x >> 5);
    int lane = threadIdx.x & 31;
    int b = node >> 11;
    int start = g_off[node];
    int cnt   = g_cnt[node];
    const int* sp = g_srcs + b*NEDGE;
    const float* hb = g_h + (size_t)b*SEQ*EMBED;
    float4 acc = make_float4(0.f, 0.f, 0.f, 0.f);
    for (int j = 0; j < cnt; j++) {
        int src = sp[start + j];
        float4 v = ((const float4*)(hb + (size_t)src*EMBED))[lane];
        acc.x += v.x; acc.y += v.y; acc.z += v.z; acc.w += v.w;
    }
    ((float4*)(g_hagg + (size_t)node*EMBED))[lane] = acc;
}

// ================= mma.sync tf32 GEMM + relu + mean-pool =================
__device__ __forceinline__ uint32_t to_tf32(float f) {
    uint32_t u;
    asm("cvt.rna.tf32.f32 %0, %1;" : "=r"(u) : "f"(f));
    return u;
}
__device__ __forceinline__ void mma_tf32(float* c, const uint32_t* a, const uint32_t* b) {
    asm volatile("mma.sync.aligned.m16n8k8.row.col.f32.tf32.tf32.f32 "
        "{%0,%1,%2,%3}, {%4,%5,%6,%7}, {%8,%9}, {%0,%1,%2,%3};"
        : "+f"(c[0]), "+f"(c[1]), "+f"(c[2]), "+f"(c[3])
        : "r"(a[0]), "r"(a[1]), "r"(a[2]), "r"(a[3]), "r"(b[0]), "r"(b[1]));
}

#define SSTRIDE 36

__global__ __launch_bounds__(256, 1)
void k_gemm(const float* __restrict__ Wupd_b) {
    __shared__ uint32_t sA[128*SSTRIDE];
    __shared__ uint32_t sB[128*SSTRIDE];
    __shared__ float sBias[256];

    int tid  = threadIdx.x;
    int wid  = tid >> 5;
    int lane = tid & 31;
    int g    = lane >> 2;
    int tg   = lane & 3;
    int rblk = blockIdx.x >> 1;
    int nb   = (blockIdx.x & 1) * 128;
    int r0   = rblk * 128;
    int b    = r0 >> 11;

    int wm = wid & 1;
    int wn = wid >> 1;
    int m0w = wm * 64;
    int n0w = wn * 32;

    if (tid < 256) sBias[tid] = Wupd_b[tid];

    float acc[4][4][4];
#pragma unroll
    for (int mi = 0; mi < 4; mi++)
#pragma unroll
        for (int ni = 0; ni < 4; ni++)
#pragma unroll
            for (int j = 0; j < 4; j++) acc[mi][ni][j] = 0.f;

    float4 pa[4], pb[4];
    {
        const float* Asrc = g_h + (size_t)r0*EMBED;
#pragma unroll
        for (int i = 0; i < 4; i++) {
            int idx = tid + i*256;
            int r = idx >> 3, q = idx & 7;
            pa[i] = *(const float4*)(Asrc + r*EMBED + q*4);
            pb[i] = *(const float4*)(g_w + (nb + r)*256 + q*4);
        }
    }

    for (int t = 0; t < 8; t++) {
        __syncthreads();
#pragma unroll
        for (int i = 0; i < 4; i++) {
            int idx = tid + i*256;
            int r = idx >> 3, q = idx & 7;
            uint4 ua = make_uint4(to_tf32(pa[i].x), to_tf32(pa[i].y),
                                  to_tf32(pa[i].z), to_tf32(pa[i].w));
            uint4 ub = make_uint4(to_tf32(pb[i].x), to_tf32(pb[i].y),
                                  to_tf32(pb[i].z), to_tf32(pb[i].w));
            *(uint4*)&sA[r*SSTRIDE + q*4] = ua;
            *(uint4*)&sB[r*SSTRIDE + q*4] = ub;
        }
        __syncthreads();
        if (t < 7) {
            int tn = t + 1;
            const float* Asrc = (tn < 4) ? (g_h    + (size_t)r0*EMBED + tn*32)
                                         : (g_hagg + (size_t)r0*EMBED + (tn-4)*32);
#pragma unroll
            for (int i = 0; i < 4; i++) {
                int idx = tid + i*256;
                int r = idx >> 3, q = idx & 7;
                pa[i] = *(const float4*)(Asrc + r*EMBED + q*4);
                pb[i] = *(const float4*)(g_w + (nb + r)*256 + tn*32 + q*4);
            }
        }
#pragma unroll
        for (int kt = 0; kt < 4; kt++) {
            int kk = kt * 8;
            uint32_t af[4][4], bf[4][2];
#pragma unroll
            for (int mi = 0; mi < 4; mi++) {
                int rb = m0w + mi*16;
                const uint32_t* pm0 = sA + (rb + g    )*SSTRIDE + kk;
                const uint32_t* pm1 = sA + (rb + g + 8)*SSTRIDE + kk;
                af[mi][0] = pm0[tg];
                af[mi][1] = pm1[tg];
                af[mi][2] = pm0[tg + 4];
                af[mi][3] = pm1[tg + 4];
            }
#pragma unroll
            for (int ni = 0; ni < 4; ni++) {
                const uint32_t* pn = sB + (n0w + ni*8 + g)*SSTRIDE + kk;
                bf[ni][0] = pn[tg];
                bf[ni][1] = pn[tg + 4];
            }
#pragma unroll
            for (int mi = 0; mi < 4; mi++)
#pragma unroll
                for (int ni = 0; ni < 4; ni++)
                    mma_tf32(acc[mi][ni], af[mi], bf[ni]);
        }
    }

#pragma unroll
    for (int ni = 0; ni < 4; ni++) {
        int col0 = nb + n0w + ni*8 + 2*tg;
        float b0 = sBias[col0], b1 = sBias[col0 + 1];
        float cs0 = 0.f, cs1 = 0.f;
#pragma unroll
        for (int mi = 0; mi < 4; mi++) {
            cs0 += fmaxf(acc[mi][ni][0] + b0, 0.f) + fmaxf(acc[mi][ni][2] + b0, 0.f);
            cs1 += fmaxf(acc[mi][ni][1] + b1, 0.f) + fmaxf(acc[mi][ni][3] + b1, 0.f);
        }
#pragma unroll
        for (int o = 4; o <= 16; o <<= 1) {
            cs0 += __shfl_xor_sync(0xffffffffu, cs0, o);
            cs1 += __shfl_xor_sync(0xffffffffu, cs1, o);
        }
        if (g == 0) {
            atomicAdd(&g_pooled[b*HID + col0],     cs0);
            atomicAdd(&g_pooled[b*HID + col0 + 1], cs1);
        }
    }
}

// ---------------- classifier ----------------
__global__ void k_cls(const float* __restrict__ cls_w, const float* __restrict__ cls_b,
                      float* __restrict__ out) {
    int tid = threadIdx.x;
    if (tid >= B_SZ*NCLS) return;
    int b = tid / NCLS, c = tid % NCLS;
    float acc = 0.f;
    const float* pp = g_pooled + b*HID;
    const float* w = cls_w + c*HID;
    for (int h = 0; h < HID; h++) acc += pp[h] * w[h];
    out[b*NCLS + c] = cls_b[c] + acc * (1.f/(float)SEQ);
}

// ---------------- launch ----------------
extern "C" void kernel_launch(void* const* d_in, const int* in_sizes, int n_in,
                              void* d_out, int out_size) {
    const int*   tokens = (const int*)  d_in[0];
    const int*   ei     = (const int*)  d_in[2];
    const float* emb    = (const float*)d_in[3];
    const float* A_log  = (const float*)d_in[4];
    const float* B_w    = (const float*)d_in[5];
    const float* C_w    = (const float*)d_in[6];
    const float* Dskip  = (const float*)d_in[7];
    const float* ln_g   = (const float*)d_in[8];
    const float* ln_b   = (const float*)d_in[9];
    const float* Wmsg   = (const float*)d_in[10];
    const float* Wupd   = (const float*)d_in[11];
    const float* Wupd_b = (const float*)d_in[12];
    const float* cls_w  = (const float*)d_in[13];
    const float* cls_b  = (const float*)d_in[14];
    float* out = (float*)d_out;

    // vocab warps = ceil(50257/4) = 12565 -> 1571 blocks of 8 warps
    const int VBLK = (VOCAB + 4*8 - 1) / (4*8);

    k_zero   <<<128, 256>>>();
    k_prep   <<<DSTATE, 128>>>(A_log);
    k_wcomb  <<<256, 256>>>(Wupd, Wmsg);
    k_vproj  <<<VBLK, 256>>>(emb, B_w);
    k_bgather<<<NROW/256, 256>>>(tokens);
    k_conv   <<<B_SZ*DSTATE, 256>>>();
    k_yln    <<<NROW/8, 256>>>(tokens, emb, C_w, Dskip, ln_g, ln_b);
    k_count  <<<512, 256>>>(ei);
    k_scan   <<<B_SZ, 256>>>();
    k_fill   <<<512, 256>>>(ei);
    k_gather <<<NROW/8, 256>>>();
    k_gemm   <<<(NROW/128)*2, 256>>>(Wupd_b);
    k_cls    <<<1, 256>>>(cls_w, cls_b, out);
}

// round 15
// speedup vs baseline: 1.2076x; 1.2076x over previous
#include <cuda_runtime.h>
#include <cuda_bf16.h>
#include <cstdint>

#define B_SZ   16
#define SEQ    2048
#define VOCAB  50257
#define EMBED  128
#define DSTATE 16
#define HID    256
#define NCLS   10
#define NEDGE  8192
#define KLEN   64
#define NROW   (B_SZ*SEQ)   // 32768

// ---------------- scratch (static device arrays; no allocation) ----------------
__device__ float g_vproj[VOCAB*DSTATE];    // emb @ B_w^T over vocab   3.2MB
__device__ float g_bmat[B_SZ*DSTATE*SEQ];  // [b][d][t]
__device__ float g_conv[NROW*DSTATE];      // [b][t][d]
__device__ float g_h[NROW*EMBED];          // LN output
__device__ float g_hagg[NROW*EMBED];       // gathered msgs
__device__ float g_w[256*256];             // combined weight [h][k]
__device__ float g_K[DSTATE*KLEN];         // conv taps
__device__ float g_pooled[B_SZ*HID];       // pooled partials
__device__ int   g_cnt[NROW];
__device__ int   g_off[NROW];
__device__ int   g_cur[NROW];
__device__ int   g_srcs[B_SZ*NEDGE];

// ---------------- zero counters / accumulators ----------------
__global__ void k_zero() {
    int i = blockIdx.x * blockDim.x + threadIdx.x;   // 32768
    g_cnt[i] = 0;
    g_cur[i] = 0;
    if (i < B_SZ*HID) g_pooled[i] = 0.f;
}

// ---------------- conv taps ----------------
__global__ void k_prep(const float* __restrict__ A_log) {
    int d = blockIdx.x;
    int tid = threadIdx.x;         // 128
    float a = expf(-expf(A_log[tid*DSTATE + d]));
    float p = 1.f;
    __shared__ float ws[4];
    for (int tau = 0; tau < KLEN; tau++) {
        float s = p;
        for (int o = 16; o; o >>= 1) s += __shfl_down_sync(0xffffffffu, s, o);
        if ((tid & 31) == 0) ws[tid >> 5] = s;
        __syncthreads();
        if (tid == 0) g_K[d*KLEN + tau] = (ws[0]+ws[1]+ws[2]+ws[3]) * (1.f/128.f);
        __syncthreads();
        p *= a;
    }
}

// ---------------- combined weight: g_w[h][k] = [Wupd1 | Wupd2@Wmsg] ----------------
__global__ void k_wcomb(const float* __restrict__ Wupd_w, const float* __restrict__ Wmsg_w) {
    int h = blockIdx.x;     // 256
    int k = threadIdx.x;    // 256
    float v;
    if (k < 128) {
        v = Wupd_w[h*384 + k];
    } else {
        int d = k - 128;
        float acc = 0.f;
        const float* w2 = Wupd_w + h*384 + 128;
        for (int hp = 0; hp < 256; hp++) acc += w2[hp] * Wmsg_w[hp*128 + d];
        v = acc;
    }
    g_w[h*256 + k] = v;
}

// ---------------- vocab projection v2: smem-tiled, broadcast LDS ----------------
// Block: 64 vocab rows. Thread (d = tid&15, rgrp = tid>>4) computes 4 rows for one d.
// sE reads: 16 threads/d-group hit same address -> broadcast. sBw stride 132 avoids
// the stride-128 16-way bank conflict (2-way residual, negligible).
#define VROWS 64
#define BWSTR 132
__global__ __launch_bounds__(256)
void k_vproj(const float* __restrict__ emb, const float* __restrict__ B_w) {
    __shared__ float sE[VROWS*EMBED];       // 32KB
    __shared__ float sBw[DSTATE*BWSTR];     // 8.25KB
    int t = threadIdx.x;
    int v0 = blockIdx.x * VROWS;
    // stage B_w with padded stride
    for (int i = t; i < DSTATE*EMBED/4; i += 256) {
        int d = i >> 5, q = i & 31;             // q indexes float4 within row
        float4 v = ((const float4*)B_w)[i];
        *(float4*)&sBw[d*BWSTR + q*4] = v;
    }
    // stage emb tile, fully coalesced
    int vmax = VOCAB - v0; if (vmax > VROWS) vmax = VROWS;
    for (int i = t; i < vmax*EMBED/4; i += 256)
        ((float4*)sE)[i] = ((const float4*)(emb + (size_t)v0*EMBED))[i];
    __syncthreads();
    int d  = t & 15;
    int r0 = (t >> 4) * 4;
    const float* bw = sBw + d*BWSTR;
    float acc[4] = {0.f, 0.f, 0.f, 0.f};
#pragma unroll
    for (int k = 0; k < EMBED; k += 4) {
        float4 b4 = *(const float4*)(bw + k);
#pragma unroll
        for (int j = 0; j < 4; j++) {
            float4 e4 = *(const float4*)(sE + (r0 + j)*EMBED + k);
            acc[j] += b4.x*e4.x + b4.y*e4.y + b4.z*e4.z + b4.w*e4.w;
        }
    }
#pragma unroll
    for (int j = 0; j < 4; j++) {
        int v = v0 + r0 + j;
        if (v < VOCAB) g_vproj[(size_t)v*DSTATE + d] = acc[j];
    }
}

// ---------------- token gather + transpose: bmat[b][d][t] = vproj[tok[b][t]][d] ----
#define TSTR 260
__global__ __launch_bounds__(256)
void k_bgather(const int* __restrict__ tokens) {
    __shared__ float st[DSTATE*TSTR];
    int r0 = blockIdx.x * 256;       // 128 blocks; 256 t's within one b
    int b  = r0 >> 11;
    int t0 = r0 & (SEQ-1);
    int t  = threadIdx.x;
    int tok = tokens[r0 + t];
    const float4* vp = (const float4*)(g_vproj + (size_t)tok*DSTATE);
    float4 f0 = vp[0], f1 = vp[1], f2 = vp[2], f3 = vp[3];
    float vals[16] = {f0.x,f0.y,f0.z,f0.w, f1.x,f1.y,f1.z,f1.w,
                      f2.x,f2.y,f2.z,f2.w, f3.x,f3.y,f3.z,f3.w};
#pragma unroll
    for (int d = 0; d < DSTATE; d++) st[d*TSTR + t] = vals[d];
    __syncthreads();
#pragma unroll
    for (int i = t; i < DSTATE*64; i += 256) {
        int d = i >> 6, tq = i & 63;
        *(float4*)(g_bmat + ((size_t)b*DSTATE + d)*SEQ + t0 + tq*4) =
            *(float4*)&st[d*TSTR + tq*4];
    }
}

// ---------------- 64-tap causal convolution (smem-staged) ----------------
__global__ void k_conv() {
    int bd = blockIdx.x;           // 256 = B*DSTATE
    int b = bd >> 4, d = bd & 15;
    __shared__ float sb[SEQ];
    __shared__ float sK[KLEN];
    int tid = threadIdx.x;         // 256
    if (tid < KLEN) sK[tid] = g_K[d*KLEN + tid];
    const float4* bm4 = (const float4*)(g_bmat + bd*SEQ);
    float4* sb4 = (float4*)sb;
    for (int i = tid; i < SEQ/4; i += 256) sb4[i] = bm4[i];
    __syncthreads();
    for (int t0 = tid; t0 < SEQ; t0 += 256) {
        float acc = 0.f;
        int tmax = t0 < (KLEN-1) ? t0 : (KLEN-1);
        for (int tau = 0; tau <= tmax; tau++) acc += sK[tau] * sb[t0 - tau];
        g_conv[(b*SEQ + t0)*DSTATE + d] = acc;
    }
}

// ---------------- y = conv@C^T + D*emb[tok], LayerNorm; warp per row ----------------
__global__ void k_yln(const int* __restrict__ tokens, const float* __restrict__ emb,
                      const float* __restrict__ C_w, const float* __restrict__ Dskip,
                      const float* __restrict__ ln_g, const float* __restrict__ ln_b) {
    int row = blockIdx.x * 8 + (threadIdx.x >> 5);   // 4096 blocks x 8 warps
    int lane = threadIdx.x & 31;
    float cv = 0.f;
    if (lane < DSTATE) cv = g_conv[row*DSTATE + lane];
    float cd[16];
#pragma unroll
    for (int d = 0; d < 16; d++) cd[d] = __shfl_sync(0xffffffffu, cv, d);
    int tok = tokens[row];
    float4 xe = *(const float4*)(emb + (size_t)tok*EMBED + lane*4);
    float4 dk = *(const float4*)(Dskip + lane*4);
    float y[4] = {dk.x*xe.x, dk.y*xe.y, dk.z*xe.z, dk.w*xe.w};
#pragma unroll
    for (int j = 0; j < 4; j++) {
        const float4* cw = (const float4*)(C_w + (lane*4 + j)*DSTATE);
        float4 c0 = cw[0], c1 = cw[1], c2 = cw[2], c3 = cw[3];
        y[j] += cd[0]*c0.x + cd[1]*c0.y + cd[2]*c0.z + cd[3]*c0.w
              + cd[4]*c1.x + cd[5]*c1.y + cd[6]*c1.z + cd[7]*c1.w
              + cd[8]*c2.x + cd[9]*c2.y + cd[10]*c2.z + cd[11]*c2.w
              + cd[12]*c3.x + cd[13]*c3.y + cd[14]*c3.z + cd[15]*c3.w;
    }
    float s  = y[0]+y[1]+y[2]+y[3];
    float s2 = y[0]*y[0]+y[1]*y[1]+y[2]*y[2]+y[3]*y[3];
    for (int o = 16; o; o >>= 1) {
        s  += __shfl_xor_sync(0xffffffffu, s,  o);
        s2 += __shfl_xor_sync(0xffffffffu, s2, o);
    }
    float mu  = s  * (1.f/128.f);
    float var = s2 * (1.f/128.f) - mu*mu;
    float r = rsqrtf(var + 1e-5f);
    float4 lg = *(const float4*)(ln_g + lane*4);
    float4 lb = *(const float4*)(ln_b + lane*4);
    float4 out;
    out.x = lg.x*(y[0]-mu)*r + lb.x;
    out.y = lg.y*(y[1]-mu)*r + lb.y;
    out.z = lg.z*(y[2]-mu)*r + lb.z;
    out.w = lg.w*(y[3]-mu)*r + lb.w;
    *(float4*)(g_h + row*EMBED + lane*4) = out;
}

// ---------------- CSR build ----------------
__global__ void k_count(const int* __restrict__ ei) {
    int idx = blockIdx.x * blockDim.x + threadIdx.x;
    int b = idx >> 13, e = idx & (NEDGE-1);
    int dst = ei[b*2*NEDGE + NEDGE + e];
    atomicAdd(&g_cnt[b*SEQ + dst], 1);
}

__global__ void k_scan() {
    int b = blockIdx.x;
    int tid = threadIdx.x;         // 256
    __shared__ int sp[256];
    int base = b*SEQ + tid*8;
    int c[8];
    int tot = 0;
#pragma unroll
    for (int j = 0; j < 8; j++) { c[j] = g_cnt[base + j]; tot += c[j]; }
    sp[tid] = tot;
    __syncthreads();
    for (int o = 1; o < 256; o <<= 1) {
        int v = (tid >= o) ? sp[tid - o] : 0;
        __syncthreads();
        sp[tid] += v;
        __syncthreads();
    }
    int run = sp[tid] - tot;
#pragma unroll
    for (int j = 0; j < 8; j++) { g_off[base + j] = run; run += c[j]; }
}

__global__ void k_fill(const int* __restrict__ ei) {
    int idx = blockIdx.x * blockDim.x + threadIdx.x;
    int b = idx >> 13, e = idx & (NEDGE-1);
    const int* eb = ei + b*2*NEDGE;
    int src = eb[e];
    int dst = eb[NEDGE + e];
    int node = b*SEQ + dst;
    int pos = g_off[node] + atomicAdd(&g_cur[node], 1);
    g_srcs[b*NEDGE + pos] = src;
}

// ---------------- gather ----------------
__global__ void k_gather() {
    int node = blockIdx.x * 8 + (threadIdx.x >> 5);
    int lane = threadIdx.x & 31;
    int b = node >> 11;
    int start = g_off[node];
    int cnt   = g_cnt[node];
    const int* sp = g_srcs + b*NEDGE;
    const float* hb = g_h + (size_t)b*SEQ*EMBED;
    float4 acc = make_float4(0.f, 0.f, 0.f, 0.f);
    for (int j = 0; j < cnt; j++) {
        int src = sp[start + j];
        float4 v = ((const float4*)(hb + (size_t)src*EMBED))[lane];
        acc.x += v.x; acc.y += v.y; acc.z += v.z; acc.w += v.w;
    }
    ((float4*)(g_hagg + (size_t)node*EMBED))[lane] = acc;
}

// ================= mma.sync tf32 GEMM + relu + mean-pool =================
__device__ __forceinline__ uint32_t to_tf32(float f) {
    uint32_t u;
    asm("cvt.rna.tf32.f32 %0, %1;" : "=r"(u) : "f"(f));
    return u;
}
__device__ __forceinline__ void mma_tf32(float* c, const uint32_t* a, const uint32_t* b) {
    asm volatile("mma.sync.aligned.m16n8k8.row.col.f32.tf32.tf32.f32 "
        "{%0,%1,%2,%3}, {%4,%5,%6,%7}, {%8,%9}, {%0,%1,%2,%3};"
        : "+f"(c[0]), "+f"(c[1]), "+f"(c[2]), "+f"(c[3])
        : "r"(a[0]), "r"(a[1]), "r"(a[2]), "r"(a[3]), "r"(b[0]), "r"(b[1]));
}

#define SSTRIDE 36

__global__ __launch_bounds__(256, 1)
void k_gemm(const float* __restrict__ Wupd_b) {
    __shared__ uint32_t sA[128*SSTRIDE];
    __shared__ uint32_t sB[128*SSTRIDE];
    __shared__ float sBias[256];

    int tid  = threadIdx.x;
    int wid  = tid >> 5;
    int lane = tid & 31;
    int g    = lane >> 2;
    int tg   = lane & 3;
    int rblk = blockIdx.x >> 1;
    int nb   = (blockIdx.x & 1) * 128;
    int r0   = rblk * 128;
    int b    = r0 >> 11;

    int wm = wid & 1;
    int wn = wid >> 1;
    int m0w = wm * 64;
    int n0w = wn * 32;

    if (tid < 256) sBias[tid] = Wupd_b[tid];

    float acc[4][4][4];
#pragma unroll
    for (int mi = 0; mi < 4; mi++)
#pragma unroll
        for (int ni = 0; ni < 4; ni++)
#pragma unroll
            for (int j = 0; j < 4; j++) acc[mi][ni][j] = 0.f;

    float4 pa[4], pb[4];
    {
        const float* Asrc = g_h + (size_t)r0*EMBED;
#pragma unroll
        for (int i = 0; i < 4; i++) {
            int idx = tid + i*256;
            int r = idx >> 3, q = idx & 7;
            pa[i] = *(const float4*)(Asrc + r*EMBED + q*4);
            pb[i] = *(const float4*)(g_w + (nb + r)*256 + q*4);
        }
    }

    for (int t = 0; t < 8; t++) {
        __syncthreads();
#pragma unroll
        for (int i = 0; i < 4; i++) {
            int idx = tid + i*256;
            int r = idx >> 3, q = idx & 7;
            uint4 ua = make_uint4(to_tf32(pa[i].x), to_tf32(pa[i].y),
                                  to_tf32(pa[i].z), to_tf32(pa[i].w));
            uint4 ub = make_uint4(to_tf32(pb[i].x), to_tf32(pb[i].y),
                                  to_tf32(pb[i].z), to_tf32(pb[i].w));
            *(uint4*)&sA[r*SSTRIDE + q*4] = ua;
            *(uint4*)&sB[r*SSTRIDE + q*4] = ub;
        }
        __syncthreads();
        if (t < 7) {
            int tn = t + 1;
            const float* Asrc = (tn < 4) ? (g_h    + (size_t)r0*EMBED + tn*32)
                                         : (g_hagg + (size_t)r0*EMBED + (tn-4)*32);
#pragma unroll
            for (int i = 0; i < 4; i++) {
                int idx = tid + i*256;
                int r = idx >> 3, q = idx & 7;
                pa[i] = *(const float4*)(Asrc + r*EMBED + q*4);
                pb[i] = *(const float4*)(g_w + (nb + r)*256 + tn*32 + q*4);
            }
        }
#pragma unroll
        for (int kt = 0; kt < 4; kt++) {
            int kk = kt * 8;
            uint32_t af[4][4], bf[4][2];
#pragma unroll
            for (int mi = 0; mi < 4; mi++) {
                int rb = m0w + mi*16;
                const uint32_t* pm0 = sA + (rb + g    )*SSTRIDE + kk;
                const uint32_t* pm1 = sA + (rb + g + 8)*SSTRIDE + kk;
                af[mi][0] = pm0[tg];
                af[mi][1] = pm1[tg];
                af[mi][2] = pm0[tg + 4];
                af[mi][3] = pm1[tg + 4];
            }
#pragma unroll
            for (int ni = 0; ni < 4; ni++) {
                const uint32_t* pn = sB + (n0w + ni*8 + g)*SSTRIDE + kk;
                bf[ni][0] = pn[tg];
                bf[ni][1] = pn[tg + 4];
            }
#pragma unroll
            for (int mi = 0; mi < 4; mi++)
#pragma unroll
                for (int ni = 0; ni < 4; ni++)
                    mma_tf32(acc[mi][ni], af[mi], bf[ni]);
        }
    }

#pragma unroll
    for (int ni = 0; ni < 4; ni++) {
        int col0 = nb + n0w + ni*8 + 2*tg;
        float b0 = sBias[col0], b1 = sBias[col0 + 1];
        float cs0 = 0.f, cs1 = 0.f;
#pragma unroll
        for (int mi = 0; mi < 4; mi++) {
            cs0 += fmaxf(acc[mi][ni][0] + b0, 0.f) + fmaxf(acc[mi][ni][2] + b0, 0.f);
            cs1 += fmaxf(acc[mi][ni][1] + b1, 0.f) + fmaxf(acc[mi][ni][3] + b1, 0.f);
        }
#pragma unroll
        for (int o = 4; o <= 16; o <<= 1) {
            cs0 += __shfl_xor_sync(0xffffffffu, cs0, o);
            cs1 += __shfl_xor_sync(0xffffffffu, cs1, o);
        }
        if (g == 0) {
            atomicAdd(&g_pooled[b*HID + col0],     cs0);
            atomicAdd(&g_pooled[b*HID + col0 + 1], cs1);
        }
    }
}

// ---------------- classifier ----------------
__global__ void k_cls(const float* __restrict__ cls_w, const float* __restrict__ cls_b,
                      float* __restrict__ out) {
    int tid = threadIdx.x;
    if (tid >= B_SZ*NCLS) return;
    int b = tid / NCLS, c = tid % NCLS;
    float acc = 0.f;
    const float* pp = g_pooled + b*HID;
    const float* w = cls_w + c*HID;
    for (int h = 0; h < HID; h++) acc += pp[h] * w[h];
    out[b*NCLS + c] = cls_b[c] + acc * (1.f/(float)SEQ);
}

// ---------------- launch ----------------
extern "C" void kernel_launch(void* const* d_in, const int* in_sizes, int n_in,
                              void* d_out, int out_size) {
    const int*   tokens = (const int*)  d_in[0];
    const int*   ei     = (const int*)  d_in[2];
    const float* emb    = (const float*)d_in[3];
    const float* A_log  = (const float*)d_in[4];
    const float* B_w    = (const float*)d_in[5];
    const float* C_w    = (const float*)d_in[6];
    const float* Dskip  = (const float*)d_in[7];
    const float* ln_g   = (const float*)d_in[8];
    const float* ln_b   = (const float*)d_in[9];
    const float* Wmsg   = (const float*)d_in[10];
    const float* Wupd   = (const float*)d_in[11];
    const float* Wupd_b = (const float*)d_in[12];
    const float* cls_w  = (const float*)d_in[13];
    const float* cls_b  = (const float*)d_in[14];
    float* out = (float*)d_out;

    const int VBLK = (VOCAB + VROWS - 1) / VROWS;   // 786

    k_zero   <<<128, 256>>>();
    k_prep   <<<DSTATE, 128>>>(A_log);
    k_wcomb  <<<256, 256>>>(Wupd, Wmsg);
    k_vproj  <<<VBLK, 256>>>(emb, B_w);
    k_bgather<<<NROW/256, 256>>>(tokens);
    k_conv   <<<B_SZ*DSTATE, 256>>>();
    k_yln    <<<NROW/8, 256>>>(tokens, emb, C_w, Dskip, ln_g, ln_b);
    k_count  <<<512, 256>>>(ei);
    k_scan   <<<B_SZ, 256>>>();
    k_fill   <<<512, 256>>>(ei);
    k_gather <<<NROW/8, 256>>>();
    k_gemm   <<<(NROW/128)*2, 256>>>(Wupd_b);
    k_cls    <<<1, 256>>>(cls_w, cls_b, out);
}

// round 16
// speedup vs baseline: 1.3464x; 1.1150x over previous
#include <cuda_runtime.h>
#include <cuda_bf16.h>
#include <cstdint>

#define B_SZ   16
#define SEQ    2048
#define VOCAB  50257
#define EMBED  128
#define DSTATE 16
#define HID    256
#define NCLS   10
#define NEDGE  8192
#define KLEN   64
#define NROW   (B_SZ*SEQ)   // 32768

// ---------------- scratch (static device arrays; no allocation) ----------------
__device__ float    g_vproj[VOCAB*DSTATE];    // emb @ B_w^T over vocab
__device__ float    g_bmat[B_SZ*DSTATE*SEQ];  // [b][d][t]
__device__ float    g_conv[NROW*DSTATE];      // [b][t][d]
__device__ uint32_t g_hb[NROW*EMBED/2];       // LN output, bf16x2   8.4MB
__device__ uint32_t g_haggb[NROW*EMBED/2];    // gathered msgs, bf16x2
__device__ uint32_t g_whb[256*128];           // combined weight [h][k] bf16x2
__device__ float    g_K[DSTATE*KLEN];         // conv taps
__device__ float    g_pooled[B_SZ*HID];       // pooled partials
__device__ int      g_cnt[NROW];
__device__ int      g_off[NROW];
__device__ int      g_cur[NROW];
__device__ int      g_srcs[B_SZ*NEDGE];

// pack two fp32 -> bf16x2 (lo = first arg, hi = second)
__device__ __forceinline__ uint32_t bf2(float lo, float hi) {
    uint32_t r;
    asm("cvt.rn.bf16x2.f32 %0, %1, %2;" : "=r"(r) : "f"(hi), "f"(lo));
    return r;
}

// ---------------- merged preamble: zero | conv taps | combined weight ----------------
__global__ void k_pre(const float* __restrict__ A_log,
                      const float* __restrict__ Wupd_w, const float* __restrict__ Wmsg_w) {
    int bid = blockIdx.x;
    int tid = threadIdx.x;
    if (bid < 128) {                       // zero counters/accumulators
        int i = bid*256 + tid;
        g_cnt[i] = 0;
        g_cur[i] = 0;
        if (i < B_SZ*HID) g_pooled[i] = 0.f;
    } else if (bid < 144) {                // conv taps, d = bid-128
        int d = bid - 128;
        float a = 0.f;
        if (tid < 128) a = expf(-expf(A_log[tid*DSTATE + d]));
        float p = (tid < 128) ? 1.f : 0.f;
        __shared__ float ws[4];
        int wid = tid >> 5, l = tid & 31;
        for (int tau = 0; tau < KLEN; tau++) {
            float s = p;
            for (int o = 16; o; o >>= 1) s += __shfl_down_sync(0xffffffffu, s, o);
            if (l == 0 && wid < 4) ws[wid] = s;
            __syncthreads();
            if (tid == 0) g_K[d*KLEN + tau] = (ws[0]+ws[1]+ws[2]+ws[3]) * (1.f/128.f);
            __syncthreads();
            p *= a;
        }
    } else {                               // combined weight (packed bf16), h = bid-144
        int h = bid - 144;
        if (tid < 128) {
            int j = tid;                   // uint32 column, covers k = 2j, 2j+1
            float v[2];
#pragma unroll
            for (int e = 0; e < 2; e++) {
                int k = 2*j + e;
                if (k < 128) {
                    v[e] = Wupd_w[h*384 + k];
                } else {
                    int d = k - 128;
                    float acc = 0.f;
                    const float* w2 = Wupd_w + h*384 + 128;
                    for (int hp = 0; hp < 256; hp++) acc += w2[hp] * Wmsg_w[hp*128 + d];
                    v[e] = acc;
                }
            }
            g_whb[h*128 + j] = bf2(v[0], v[1]);
        }
    }
}

// ---------------- vocab projection: smem-tiled, broadcast LDS ----------------
#define VROWS 64
#define BWSTR 132
__global__ __launch_bounds__(256)
void k_vproj(const float* __restrict__ emb, const float* __restrict__ B_w) {
    __shared__ float sE[VROWS*EMBED];       // 32KB
    __shared__ float sBw[DSTATE*BWSTR];     // 8.25KB
    int t = threadIdx.x;
    int v0 = blockIdx.x * VROWS;
    for (int i = t; i < DSTATE*EMBED/4; i += 256) {
        int d = i >> 5, q = i & 31;
        float4 v = ((const float4*)B_w)[i];
        *(float4*)&sBw[d*BWSTR + q*4] = v;
    }
    int vmax = VOCAB - v0; if (vmax > VROWS) vmax = VROWS;
    for (int i = t; i < vmax*EMBED/4; i += 256)
        ((float4*)sE)[i] = ((const float4*)(emb + (size_t)v0*EMBED))[i];
    __syncthreads();
    int d  = t & 15;
    int r0 = (t >> 4) * 4;
    const float* bw = sBw + d*BWSTR;
    float acc[4] = {0.f, 0.f, 0.f, 0.f};
#pragma unroll
    for (int k = 0; k < EMBED; k += 4) {
        float4 b4 = *(const float4*)(bw + k);
#pragma unroll
        for (int j = 0; j < 4; j++) {
            float4 e4 = *(const float4*)(sE + (r0 + j)*EMBED + k);
            acc[j] += b4.x*e4.x + b4.y*e4.y + b4.z*e4.z + b4.w*e4.w;
        }
    }
#pragma unroll
    for (int j = 0; j < 4; j++) {
        int v = v0 + r0 + j;
        if (v < VOCAB) g_vproj[(size_t)v*DSTATE + d] = acc[j];
    }
}

// ---------------- token gather + transpose: bmat[b][d][t] = vproj[tok[b][t]][d] ----
#define TSTR 260
__global__ __launch_bounds__(256)
void k_bgather(const int* __restrict__ tokens) {
    __shared__ float st[DSTATE*TSTR];
    int r0 = blockIdx.x * 256;
    int b  = r0 >> 11;
    int t0 = r0 & (SEQ-1);
    int t  = threadIdx.x;
    int tok = tokens[r0 + t];
    const float4* vp = (const float4*)(g_vproj + (size_t)tok*DSTATE);
    float4 f0 = vp[0], f1 = vp[1], f2 = vp[2], f3 = vp[3];
    float vals[16] = {f0.x,f0.y,f0.z,f0.w, f1.x,f1.y,f1.z,f1.w,
                      f2.x,f2.y,f2.z,f2.w, f3.x,f3.y,f3.z,f3.w};
#pragma unroll
    for (int d = 0; d < DSTATE; d++) st[d*TSTR + t] = vals[d];
    __syncthreads();
#pragma unroll
    for (int i = t; i < DSTATE*64; i += 256) {
        int d = i >> 6, tq = i & 63;
        *(float4*)(g_bmat + ((size_t)b*DSTATE + d)*SEQ + t0 + tq*4) =
            *(float4*)&st[d*TSTR + tq*4];
    }
}

// ---------------- 64-tap causal convolution (smem-staged) ----------------
__global__ void k_conv() {
    int bd = blockIdx.x;
    int b = bd >> 4, d = bd & 15;
    __shared__ float sb[SEQ];
    __shared__ float sK[KLEN];
    int tid = threadIdx.x;
    if (tid < KLEN) sK[tid] = g_K[d*KLEN + tid];
    const float4* bm4 = (const float4*)(g_bmat + bd*SEQ);
    float4* sb4 = (float4*)sb;
    for (int i = tid; i < SEQ/4; i += 256) sb4[i] = bm4[i];
    __syncthreads();
    for (int t0 = tid; t0 < SEQ; t0 += 256) {
        float acc = 0.f;
        int tmax = t0 < (KLEN-1) ? t0 : (KLEN-1);
        for (int tau = 0; tau <= tmax; tau++) acc += sK[tau] * sb[t0 - tau];
        g_conv[(b*SEQ + t0)*DSTATE + d] = acc;
    }
}

// ---------------- y = conv@C^T + D*emb[tok], LayerNorm -> bf16; warp per row ------
__global__ void k_yln(const int* __restrict__ tokens, const float* __restrict__ emb,
                      const float* __restrict__ C_w, const float* __restrict__ Dskip,
                      const float* __restrict__ ln_g, const float* __restrict__ ln_b) {
    int row = blockIdx.x * 8 + (threadIdx.x >> 5);
    int lane = threadIdx.x & 31;
    float cv = 0.f;
    if (lane < DSTATE) cv = g_conv[row*DSTATE + lane];
    float cd[16];
#pragma unroll
    for (int d = 0; d < 16; d++) cd[d] = __shfl_sync(0xffffffffu, cv, d);
    int tok = tokens[row];
    float4 xe = *(const float4*)(emb + (size_t)tok*EMBED + lane*4);
    float4 dk = *(const float4*)(Dskip + lane*4);
    float y[4] = {dk.x*xe.x, dk.y*xe.y, dk.z*xe.z, dk.w*xe.w};
#pragma unroll
    for (int j = 0; j < 4; j++) {
        const float4* cw = (const float4*)(C_w + (lane*4 + j)*DSTATE);
        float4 c0 = cw[0], c1 = cw[1], c2 = cw[2], c3 = cw[3];
        y[j] += cd[0]*c0.x + cd[1]*c0.y + cd[2]*c0.z + cd[3]*c0.w
              + cd[4]*c1.x + cd[5]*c1.y + cd[6]*c1.z + cd[7]*c1.w
              + cd[8]*c2.x + cd[9]*c2.y + cd[10]*c2.z + cd[11]*c2.w
              + cd[12]*c3.x + cd[13]*c3.y + cd[14]*c3.z + cd[15]*c3.w;
    }
    float s  = y[0]+y[1]+y[2]+y[3];
    float s2 = y[0]*y[0]+y[1]*y[1]+y[2]*y[2]+y[3]*y[3];
    for (int o = 16; o; o >>= 1) {
        s  += __shfl_xor_sync(0xffffffffu, s,  o);
        s2 += __shfl_xor_sync(0xffffffffu, s2, o);
    }
    float mu  = s  * (1.f/128.f);
    float var = s2 * (1.f/128.f) - mu*mu;
    float r = rsqrtf(var + 1e-5f);
    float4 lg = *(const float4*)(ln_g + lane*4);
    float4 lb = *(const float4*)(ln_b + lane*4);
    float o0 = lg.x*(y[0]-mu)*r + lb.x;
    float o1 = lg.y*(y[1]-mu)*r + lb.y;
    float o2 = lg.z*(y[2]-mu)*r + lb.z;
    float o3 = lg.w*(y[3]-mu)*r + lb.w;
    *(uint2*)(g_hb + (size_t)row*64 + lane*2) = make_uint2(bf2(o0, o1), bf2(o2, o3));
}

// ---------------- CSR build ----------------
__global__ void k_count(const int* __restrict__ ei) {
    int idx = blockIdx.x * blockDim.x + threadIdx.x;
    int b = idx >> 13, e = idx & (NEDGE-1);
    int dst = ei[b*2*NEDGE + NEDGE + e];
    atomicAdd(&g_cnt[b*SEQ + dst], 1);
}

__global__ void k_scan() {
    int b = blockIdx.x;
    int tid = threadIdx.x;
    __shared__ int sp[256];
    int base = b*SEQ + tid*8;
    int c[8];
    int tot = 0;
#pragma unroll
    for (int j = 0; j < 8; j++) { c[j] = g_cnt[base + j]; tot += c[j]; }
    sp[tid] = tot;
    __syncthreads();
    for (int o = 1; o < 256; o <<= 1) {
        int v = (tid >= o) ? sp[tid - o] : 0;
        __syncthreads();
        sp[tid] += v;
        __syncthreads();
    }
    int run = sp[tid] - tot;
#pragma unroll
    for (int j = 0; j < 8; j++) { g_off[base + j] = run; run += c[j]; }
}

__global__ void k_fill(const int* __restrict__ ei) {
    int idx = blockIdx.x * blockDim.x + threadIdx.x;
    int b = idx >> 13, e = idx & (NEDGE-1);
    const int* eb = ei + b*2*NEDGE;
    int src = eb[e];
    int dst = eb[NEDGE + e];
    int node = b*SEQ + dst;
    int pos = g_off[node] + atomicAdd(&g_cur[node], 1);
    g_srcs[b*NEDGE + pos] = src;
}

// ---------------- gather (bf16 rows, fp32 accumulate) ----------------
__global__ void k_gather() {
    int node = blockIdx.x * 8 + (threadIdx.x >> 5);
    int lane = threadIdx.x & 31;
    int b = node >> 11;
    int start = g_off[node];
    int cnt   = g_cnt[node];
    const int* sp = g_srcs + b*NEDGE;
    const uint32_t* hb = g_hb + (size_t)b*SEQ*64;
    float a0 = 0.f, a1 = 0.f, a2 = 0.f, a3 = 0.f;
    for (int j = 0; j < cnt; j++) {
        int src = sp[start + j];
        uint2 v = *(const uint2*)(hb + (size_t)src*64 + lane*2);
        float2 f0 = __bfloat1622float2(*reinterpret_cast<__nv_bfloat162*>(&v.x));
        float2 f1 = __bfloat1622float2(*reinterpret_cast<__nv_bfloat162*>(&v.y));
        a0 += f0.x; a1 += f0.y; a2 += f1.x; a3 += f1.y;
    }
    *(uint2*)(g_haggb + (size_t)node*64 + lane*2) = make_uint2(bf2(a0, a1), bf2(a2, a3));
}

// ================= mma.sync bf16 GEMM + relu + mean-pool =================
// C[32768x256] = [h|hagg]_bf16 @ W_bf16^T, relu(+bias), mean-pool over rows.
// CTA tile 128M x 128N; K=256 in 8 chunks of 32 bf16 (16 uint32/row, stride 20).
__device__ __forceinline__ void mma_bf16(float* c, const uint32_t* a, const uint32_t* b) {
    asm volatile("mma.sync.aligned.m16n8k16.row.col.f32.bf16.bf16.f32 "
        "{%0,%1,%2,%3}, {%4,%5,%6,%7}, {%8,%9}, {%0,%1,%2,%3};"
        : "+f"(c[0]), "+f"(c[1]), "+f"(c[2]), "+f"(c[3])
        : "r"(a[0]), "r"(a[1]), "r"(a[2]), "r"(a[3]), "r"(b[0]), "r"(b[1]));
}

#define SST 20

__global__ __launch_bounds__(256, 1)
void k_gemm(const float* __restrict__ Wupd_b) {
    __shared__ uint32_t sA[128*SST];    // 10240B
    __shared__ uint32_t sB[128*SST];
    __shared__ float sBias[256];

    int tid  = threadIdx.x;
    int wid  = tid >> 5;
    int lane = tid & 31;
    int g    = lane >> 2;
    int tg   = lane & 3;
    int rblk = blockIdx.x >> 1;
    int nb   = (blockIdx.x & 1) * 128;
    int r0   = rblk * 128;
    int b    = r0 >> 11;

    int wm = wid & 1;
    int wn = wid >> 1;
    int m0w = wm * 64;
    int n0w = wn * 32;

    sBias[tid] = Wupd_b[tid];

    float acc[4][4][4];
#pragma unroll
    for (int mi = 0; mi < 4; mi++)
#pragma unroll
        for (int ni = 0; ni < 4; ni++)
#pragma unroll
            for (int j = 0; j < 4; j++) acc[mi][ni][j] = 0.f;

    uint4 pa[2], pb[2];
    {
#pragma unroll
        for (int i = 0; i < 2; i++) {
            int idx = tid + i*256;
            int r = idx >> 2, q = idx & 3;
            pa[i] = *(const uint4*)(g_hb  + (size_t)(r0 + r)*64 + q*4);
            pb[i] = *(const uint4*)(g_whb + (size_t)(nb + r)*128 + q*4);
        }
    }

    for (int t = 0; t < 8; t++) {
        __syncthreads();
#pragma unroll
        for (int i = 0; i < 2; i++) {
            int idx = tid + i*256;
            int r = idx >> 2, q = idx & 3;
            *(uint4*)&sA[r*SST + q*4] = pa[i];
            *(uint4*)&sB[r*SST + q*4] = pb[i];
        }
        __syncthreads();
        if (t < 7) {
            int tn = t + 1;
#pragma unroll
            for (int i = 0; i < 2; i++) {
                int idx = tid + i*256;
                int r = idx >> 2, q = idx & 3;
                pa[i] = (tn < 4)
                    ? *(const uint4*)(g_hb    + (size_t)(r0 + r)*64 + tn*16 + q*4)
                    : *(const uint4*)(g_haggb + (size_t)(r0 + r)*64 + (tn-4)*16 + q*4);
                pb[i] = *(const uint4*)(g_whb + (size_t)(nb + r)*128 + tn*16 + q*4);
            }
        }
        // two k16 steps per 32-bf16 chunk
#pragma unroll
        for (int ks = 0; ks < 2; ks++) {
            int kk = ks * 8;
            uint32_t af[4][4], bf[4][2];
#pragma unroll
            for (int mi = 0; mi < 4; mi++) {
                int rb = m0w + mi*16;
                const uint32_t* pm0 = sA + (rb + g    )*SST + kk + tg;
                const uint32_t* pm1 = sA + (rb + g + 8)*SST + kk + tg;
                af[mi][0] = pm0[0];
                af[mi][1] = pm1[0];
                af[mi][2] = pm0[4];
                af[mi][3] = pm1[4];
            }
#pragma unroll
            for (int ni = 0; ni < 4; ni++) {
                const uint32_t* pn = sB + (n0w + ni*8 + g)*SST + kk + tg;
                bf[ni][0] = pn[0];
                bf[ni][1] = pn[4];
            }
#pragma unroll
            for (int mi = 0; mi < 4; mi++)
#pragma unroll
                for (int ni = 0; ni < 4; ni++)
                    mma_bf16(acc[mi][ni], af[mi], bf[ni]);
        }
    }

    // epilogue: bias + relu, sum rows, reduce across g, atomic to pooled
#pragma unroll
    for (int ni = 0; ni < 4; ni++) {
        int col0 = nb + n0w + ni*8 + 2*tg;
        float b0 = sBias[col0], b1 = sBias[col0 + 1];
        float cs0 = 0.f, cs1 = 0.f;
#pragma unroll
        for (int mi = 0; mi < 4; mi++) {
            cs0 += fmaxf(acc[mi][ni][0] + b0, 0.f) + fmaxf(acc[mi][ni][2] + b0, 0.f);
            cs1 += fmaxf(acc[mi][ni][1] + b1, 0.f) + fmaxf(acc[mi][ni][3] + b1, 0.f);
        }
#pragma unroll
        for (int o = 4; o <= 16; o <<= 1) {
            cs0 += __shfl_xor_sync(0xffffffffu, cs0, o);
            cs1 += __shfl_xor_sync(0xffffffffu, cs1, o);
        }
        if (g == 0) {
            atomicAdd(&g_pooled[b*HID + col0],     cs0);
            atomicAdd(&g_pooled[b*HID + col0 + 1], cs1);
        }
    }
}

// ---------------- classifier ----------------
__global__ void k_cls(const float* __restrict__ cls_w, const float* __restrict__ cls_b,
                      float* __restrict__ out) {
    int tid = threadIdx.x;
    if (tid >= B_SZ*NCLS) return;
    int b = tid / NCLS, c = tid % NCLS;
    float acc = 0.f;
    const float* pp = g_pooled + b*HID;
    const float* w = cls_w + c*HID;
    for (int h = 0; h < HID; h++) acc += pp[h] * w[h];
    out[b*NCLS + c] = cls_b[c] + acc * (1.f/(float)SEQ);
}

// ---------------- launch ----------------
extern "C" void kernel_launch(void* const* d_in, const int* in_sizes, int n_in,
                              void* d_out, int out_size) {
    const int*   tokens = (const int*)  d_in[0];
    const int*   ei     = (const int*)  d_in[2];
    const float* emb    = (const float*)d_in[3];
    const float* A_log  = (const float*)d_in[4];
    const float* B_w    = (const float*)d_in[5];
    const float* C_w    = (const float*)d_in[6];
    const float* Dskip  = (const float*)d_in[7];
    const float* ln_g   = (const float*)d_in[8];
    const float* ln_b   = (const float*)d_in[9];
    const float* Wmsg   = (const float*)d_in[10];
    const float* Wupd   = (const float*)d_in[11];
    const float* Wupd_b = (const float*)d_in[12];
    const float* cls_w  = (const float*)d_in[13];
    const float* cls_b  = (const float*)d_in[14];
    float* out = (float*)d_out;

    const int VBLK = (VOCAB + VROWS - 1) / VROWS;   // 786

    k_pre    <<<400, 256>>>(A_log, Wupd, Wmsg);
    k_vproj  <<<VBLK, 256>>>(emb, B_w);
    k_bgather<<<NROW/256, 256>>>(tokens);
    k_conv   <<<B_SZ*DSTATE, 256>>>();
    k_yln    <<<NROW/8, 256>>>(tokens, emb, C_w, Dskip, ln_g, ln_b);
    k_count  <<<512, 256>>>(ei);
    k_scan   <<<B_SZ, 256>>>();
    k_fill   <<<512, 256>>>(ei);
    k_gather <<<NROW/8, 256>>>();
    k_gemm   <<<(NROW/128)*2, 256>>>(Wupd_b);
    k_cls    <<<1, 256>>>(cls_w, cls_b, out);
}

// round 17
// speedup vs baseline: 1.4630x; 1.0866x over previous
#include <cuda_runtime.h>
#include <cuda_bf16.h>
#include <cstdint>

#define B_SZ   16
#define SEQ    2048
#define VOCAB  50257
#define EMBED  128
#define DSTATE 16
#define HID    256
#define NCLS   10
#define NEDGE  8192
#define KLEN   64
#define NROW   (B_SZ*SEQ)   // 32768

// ---------------- scratch (static device arrays; no allocation) ----------------
__device__ float    g_vproj[VOCAB*DSTATE];
__device__ float    g_bmat[B_SZ*DSTATE*SEQ];  // [b][d][t]
__device__ float    g_conv[NROW*DSTATE];      // [b][t][d]
__device__ uint32_t g_hb[NROW*EMBED/2];       // LN output, bf16x2
__device__ uint32_t g_haggb[NROW*EMBED/2];    // gathered msgs, bf16x2
__device__ uint32_t g_whb[256*128];           // combined weight [h][k] bf16x2
__device__ float    g_K[DSTATE*KLEN];
__device__ float    g_pooled[B_SZ*HID];       // zeroed at end of k_cls
__device__ int      g_cnt[NROW];              // zeroed at end of k_gather
__device__ int      g_off[NROW];
__device__ int      g_cur[NROW];              // zeroed at end of k_gather
__device__ int      g_srcs[B_SZ*NEDGE];

__device__ __forceinline__ uint32_t bf2(float lo, float hi) {
    uint32_t r;
    asm("cvt.rn.bf16x2.f32 %0, %1, %2;" : "=r"(r) : "f"(hi), "f"(lo));
    return r;
}

// ================= Stage 1: count | conv taps | combined weight | vproj =========
// blocks [0,512): edge count      [512,528): taps     [528,784): wcomb
// blocks [784,1570): vproj (64 vocab rows each)
#define VROWS 64
#define BWSTR 132
#define S1_VP0 784
__global__ __launch_bounds__(256)
void k_s1(const float* __restrict__ A_log,
          const float* __restrict__ Wupd_w, const float* __restrict__ Wmsg_w,
          const int* __restrict__ ei,
          const float* __restrict__ emb, const float* __restrict__ B_w) {
    __shared__ float sE[VROWS*EMBED];       // 32KB (vproj); reused as ws by taps
    __shared__ float sBw[DSTATE*BWSTR];     // 8.25KB
    int bid = blockIdx.x;
    int tid = threadIdx.x;
    if (bid < 512) {                         // edge count (cnt zeroed by prev gather)
        int idx = bid*256 + tid;
        int b = idx >> 13, e = idx & (NEDGE-1);
        int dst = ei[b*2*NEDGE + NEDGE + e];
        atomicAdd(&g_cnt[b*SEQ + dst], 1);
    } else if (bid < 528) {                  // conv taps, d = bid-512
        int d = bid - 512;
        float a = 0.f;
        if (tid < 128) a = expf(-expf(A_log[tid*DSTATE + d]));
        float p = (tid < 128) ? 1.f : 0.f;
        float* ws = sE;
        int wid = tid >> 5, l = tid & 31;
        for (int tau = 0; tau < KLEN; tau++) {
            float s = p;
            for (int o = 16; o; o >>= 1) s += __shfl_down_sync(0xffffffffu, s, o);
            if (l == 0 && wid < 4) ws[wid] = s;
            __syncthreads();
            if (tid == 0) g_K[d*KLEN + tau] = (ws[0]+ws[1]+ws[2]+ws[3]) * (1.f/128.f);
            __syncthreads();
            p *= a;
        }
    } else if (bid < S1_VP0) {               // combined weight, h = bid-528
        int h = bid - 528;
        if (tid < 128) {
            int j = tid;
            float v[2];
#pragma unroll
            for (int e = 0; e < 2; e++) {
                int k = 2*j + e;
                if (k < 128) {
                    v[e] = Wupd_w[h*384 + k];
                } else {
                    int d = k - 128;
                    float acc = 0.f;
                    const float* w2 = Wupd_w + h*384 + 128;
                    for (int hp = 0; hp < 256; hp++) acc += w2[hp] * Wmsg_w[hp*128 + d];
                    v[e] = acc;
                }
            }
            g_whb[h*128 + j] = bf2(v[0], v[1]);
        }
    } else {                                 // vproj
        int v0 = (bid - S1_VP0) * VROWS;
        for (int i = tid; i < DSTATE*EMBED/4; i += 256) {
            int d = i >> 5, q = i & 31;
            float4 v = ((const float4*)B_w)[i];
            *(float4*)&sBw[d*BWSTR + q*4] = v;
        }
        int vmax = VOCAB - v0; if (vmax > VROWS) vmax = VROWS;
        for (int i = tid; i < vmax*EMBED/4; i += 256)
            ((float4*)sE)[i] = ((const float4*)(emb + (size_t)v0*EMBED))[i];
        __syncthreads();
        int d  = tid & 15;
        int r0 = (tid >> 4) * 4;
        const float* bw = sBw + d*BWSTR;
        float acc[4] = {0.f, 0.f, 0.f, 0.f};
#pragma unroll
        for (int k = 0; k < EMBED; k += 4) {
            float4 b4 = *(const float4*)(bw + k);
#pragma unroll
            for (int j = 0; j < 4; j++) {
                float4 e4 = *(const float4*)(sE + (r0 + j)*EMBED + k);
                acc[j] += b4.x*e4.x + b4.y*e4.y + b4.z*e4.z + b4.w*e4.w;
            }
        }
#pragma unroll
        for (int j = 0; j < 4; j++) {
            int v = v0 + r0 + j;
            if (v < VOCAB) g_vproj[(size_t)v*DSTATE + d] = acc[j];
        }
    }
}

// ================= Stage 2: bgather | scan =========
// blocks [0,128): bgather (256 tokens each)   [128,144): per-batch scan
#define TSTR 260
__global__ __launch_bounds__(256)
void k_s2(const int* __restrict__ tokens) {
    __shared__ float st[DSTATE*TSTR];       // 16.6KB; scan reuses as int
    int bid = blockIdx.x;
    int t = threadIdx.x;
    if (bid < 128) {                         // bgather + transpose
        int r0 = bid * 256;
        int b  = r0 >> 11;
        int t0 = r0 & (SEQ-1);
        int tok = tokens[r0 + t];
        const float4* vp = (const float4*)(g_vproj + (size_t)tok*DSTATE);
        float4 f0 = vp[0], f1 = vp[1], f2 = vp[2], f3 = vp[3];
        float vals[16] = {f0.x,f0.y,f0.z,f0.w, f1.x,f1.y,f1.z,f1.w,
                          f2.x,f2.y,f2.z,f2.w, f3.x,f3.y,f3.z,f3.w};
#pragma unroll
        for (int d = 0; d < DSTATE; d++) st[d*TSTR + t] = vals[d];
        __syncthreads();
#pragma unroll
        for (int i = t; i < DSTATE*64; i += 256) {
            int d = i >> 6, tq = i & 63;
            *(float4*)(g_bmat + ((size_t)b*DSTATE + d)*SEQ + t0 + tq*4) =
                *(float4*)&st[d*TSTR + tq*4];
        }
    } else {                                 // scan, b = bid-128
        int b = bid - 128;
        int* sp = (int*)st;
        int base = b*SEQ + t*8;
        int c[8];
        int tot = 0;
#pragma unroll
        for (int j = 0; j < 8; j++) { c[j] = g_cnt[base + j]; tot += c[j]; }
        sp[t] = tot;
        __syncthreads();
        for (int o = 1; o < 256; o <<= 1) {
            int v = (t >= o) ? sp[t - o] : 0;
            __syncthreads();
            sp[t] += v;
            __syncthreads();
        }
        int run = sp[t] - tot;
#pragma unroll
        for (int j = 0; j < 8; j++) { g_off[base + j] = run; run += c[j]; }
    }
}

// ================= Stage 3: conv (4-way t-split, halo) | fill =========
// blocks [0,1024): conv — block = (bd, quarter)    [1024,1536): fill
__global__ __launch_bounds__(256)
void k_s3(const int* __restrict__ ei) {
    __shared__ float sb[512 + 64];
    __shared__ float sK[KLEN];
    int bid = blockIdx.x;
    int tid = threadIdx.x;
    if (bid < 1024) {                        // conv
        int bd = bid >> 2, q = bid & 3;
        int b = bd >> 4, d = bd & 15;
        int tstart = q * 512;
        if (tid < KLEN) sK[tid] = g_K[d*KLEN + tid];
        const float* bm = g_bmat + (size_t)bd*SEQ;
        for (int i = tid; i < 512 + 63; i += 256) {
            int tt = tstart - 63 + i;
            sb[i] = (tt >= 0) ? bm[tt] : 0.f;
        }
        __syncthreads();
#pragma unroll
        for (int jj = 0; jj < 2; jj++) {
            int j = tid + jj*256;
            float acc = 0.f;
            const float* sp = sb + 63 + j;
#pragma unroll
            for (int tau = 0; tau < KLEN; tau++) acc += sK[tau] * sp[-tau];
            g_conv[((size_t)b*SEQ + tstart + j)*DSTATE + d] = acc;
        }
    } else {                                 // fill
        int idx = (bid - 1024)*256 + tid;
        int b = idx >> 13, e = idx & (NEDGE-1);
        const int* eb = ei + b*2*NEDGE;
        int src = eb[e];
        int dst = eb[NEDGE + e];
        int node = b*SEQ + dst;
        int pos = g_off[node] + atomicAdd(&g_cur[node], 1);
        g_srcs[b*NEDGE + pos] = src;
    }
}

// ---------------- y = conv@C^T + D*emb[tok], LayerNorm -> bf16; warp per row ------
__global__ void k_yln(const int* __restrict__ tokens, const float* __restrict__ emb,
                      const float* __restrict__ C_w, const float* __restrict__ Dskip,
                      const float* __restrict__ ln_g, const float* __restrict__ ln_b) {
    int row = blockIdx.x * 8 + (threadIdx.x >> 5);
    int lane = threadIdx.x & 31;
    float cv = 0.f;
    if (lane < DSTATE) cv = g_conv[(size_t)row*DSTATE + lane];
    float cd[16];
#pragma unroll
    for (int d = 0; d < 16; d++) cd[d] = __shfl_sync(0xffffffffu, cv, d);
    int tok = tokens[row];
    float4 xe = *(const float4*)(emb + (size_t)tok*EMBED + lane*4);
    float4 dk = *(const float4*)(Dskip + lane*4);
    float y[4] = {dk.x*xe.x, dk.y*xe.y, dk.z*xe.z, dk.w*xe.w};
#pragma unroll
    for (int j = 0; j < 4; j++) {
        const float4* cw = (const float4*)(C_w + (lane*4 + j)*DSTATE);
        float4 c0 = cw[0], c1 = cw[1], c2 = cw[2], c3 = cw[3];
        y[j] += cd[0]*c0.x + cd[1]*c0.y + cd[2]*c0.z + cd[3]*c0.w
              + cd[4]*c1.x + cd[5]*c1.y + cd[6]*c1.z + cd[7]*c1.w
              + cd[8]*c2.x + cd[9]*c2.y + cd[10]*c2.z + cd[11]*c2.w
              + cd[12]*c3.x + cd[13]*c3.y + cd[14]*c3.z + cd[15]*c3.w;
    }
    float s  = y[0]+y[1]+y[2]+y[3];
    float s2 = y[0]*y[0]+y[1]*y[1]+y[2]*y[2]+y[3]*y[3];
    for (int o = 16; o; o >>= 1) {
        s  += __shfl_xor_sync(0xffffffffu, s,  o);
        s2 += __shfl_xor_sync(0xffffffffu, s2, o);
    }
    float mu  = s  * (1.f/128.f);
    float var = s2 * (1.f/128.f) - mu*mu;
    float r = rsqrtf(var + 1e-5f);
    float4 lg = *(const float4*)(ln_g + lane*4);
    float4 lb = *(const float4*)(ln_b + lane*4);
    float o0 = lg.x*(y[0]-mu)*r + lb.x;
    float o1 = lg.y*(y[1]-mu)*r + lb.y;
    float o2 = lg.z*(y[2]-mu)*r + lb.z;
    float o3 = lg.w*(y[3]-mu)*r + lb.w;
    *(uint2*)(g_hb + (size_t)row*64 + lane*2) = make_uint2(bf2(o0, o1), bf2(o2, o3));
}

// ---------------- gather (bf16 rows, fp32 accumulate) + CSR state reset ----------
__global__ void k_gather() {
    int node = blockIdx.x * 8 + (threadIdx.x >> 5);
    int lane = threadIdx.x & 31;
    int b = node >> 11;
    int start = g_off[node];
    int cnt   = g_cnt[node];
    const int* sp = g_srcs + b*NEDGE;
    const uint32_t* hb = g_hb + (size_t)b*SEQ*64;
    float a0 = 0.f, a1 = 0.f, a2 = 0.f, a3 = 0.f;
    for (int j = 0; j < cnt; j++) {
        int src = sp[start + j];
        uint2 v = *(const uint2*)(hb + (size_t)src*64 + lane*2);
        float2 f0 = __bfloat1622float2(*reinterpret_cast<__nv_bfloat162*>(&v.x));
        float2 f1 = __bfloat1622float2(*reinterpret_cast<__nv_bfloat162*>(&v.y));
        a0 += f0.x; a1 += f0.y; a2 += f1.x; a3 += f1.y;
    }
    *(uint2*)(g_haggb + (size_t)node*64 + lane*2) = make_uint2(bf2(a0, a1), bf2(a2, a3));
    if (lane == 0) { g_cnt[node] = 0; g_cur[node] = 0; }   // reset for next replay
}

// ================= mma.sync bf16 GEMM + relu + mean-pool =================
__device__ __forceinline__ void mma_bf16(float* c, const uint32_t* a, const uint32_t* b) {
    asm volatile("mma.sync.aligned.m16n8k16.row.col.f32.bf16.bf16.f32 "
        "{%0,%1,%2,%3}, {%4,%5,%6,%7}, {%8,%9}, {%0,%1,%2,%3};"
        : "+f"(c[0]), "+f"(c[1]), "+f"(c[2]), "+f"(c[3])
        : "r"(a[0]), "r"(a[1]), "r"(a[2]), "r"(a[3]), "r"(b[0]), "r"(b[1]));
}

#define SST 20

__global__ __launch_bounds__(256, 1)
void k_gemm(const float* __restrict__ Wupd_b) {
    __shared__ uint32_t sA[128*SST];
    __shared__ uint32_t sB[128*SST];
    __shared__ float sBias[256];

    int tid  = threadIdx.x;
    int wid  = tid >> 5;
    int lane = tid & 31;
    int g    = lane >> 2;
    int tg   = lane & 3;
    int rblk = blockIdx.x >> 1;
    int nb   = (blockIdx.x & 1) * 128;
    int r0   = rblk * 128;
    int b    = r0 >> 11;

    int wm = wid & 1;
    int wn = wid >> 1;
    int m0w = wm * 64;
    int n0w = wn * 32;

    sBias[tid] = Wupd_b[tid];

    float acc[4][4][4];
#pragma unroll
    for (int mi = 0; mi < 4; mi++)
#pragma unroll
        for (int ni = 0; ni < 4; ni++)
#pragma unroll
            for (int j = 0; j < 4; j++) acc[mi][ni][j] = 0.f;

    uint4 pa[2], pb[2];
    {
#pragma unroll
        for (int i = 0; i < 2; i++) {
            int idx = tid + i*256;
            int r = idx >> 2, q = idx & 3;
            pa[i] = *(const uint4*)(g_hb  + (size_t)(r0 + r)*64 + q*4);
            pb[i] = *(const uint4*)(g_whb + (size_t)(nb + r)*128 + q*4);
        }
    }

    for (int t = 0; t < 8; t++) {
        __syncthreads();
#pragma unroll
        for (int i = 0; i < 2; i++) {
            int idx = tid + i*256;
            int r = idx >> 2, q = idx & 3;
            *(uint4*)&sA[r*SST + q*4] = pa[i];
            *(uint4*)&sB[r*SST + q*4] = pb[i];
        }
        __syncthreads();
        if (t < 7) {
            int tn = t + 1;
#pragma unroll
            for (int i = 0; i < 2; i++) {
                int idx = tid + i*256;
                int r = idx >> 2, q = idx & 3;
                pa[i] = (tn < 4)
                    ? *(const uint4*)(g_hb    + (size_t)(r0 + r)*64 + tn*16 + q*4)
                    : *(const uint4*)(g_haggb + (size_t)(r0 + r)*64 + (tn-4)*16 + q*4);
                pb[i] = *(const uint4*)(g_whb + (size_t)(nb + r)*128 + tn*16 + q*4);
            }
        }
#pragma unroll
        for (int ks = 0; ks < 2; ks++) {
            int kk = ks * 8;
            uint32_t af[4][4], bf[4][2];
#pragma unroll
            for (int mi = 0; mi < 4; mi++) {
                int rb = m0w + mi*16;
                const uint32_t* pm0 = sA + (rb + g    )*SST + kk + tg;
                const uint32_t* pm1 = sA + (rb + g + 8)*SST + kk + tg;
                af[mi][0] = pm0[0];
                af[mi][1] = pm1[0];
                af[mi][2] = pm0[4];
                af[mi][3] = pm1[4];
            }
#pragma unroll
            for (int ni = 0; ni < 4; ni++) {
                const uint32_t* pn = sB + (n0w + ni*8 + g)*SST + kk + tg;
                bf[ni][0] = pn[0];
                bf[ni][1] = pn[4];
            }
#pragma unroll
            for (int mi = 0; mi < 4; mi++)
#pragma unroll
                for (int ni = 0; ni < 4; ni++)
                    mma_bf16(acc[mi][ni], af[mi], bf[ni]);
        }
    }

#pragma unroll
    for (int ni = 0; ni < 4; ni++) {
        int col0 = nb + n0w + ni*8 + 2*tg;
        float b0 = sBias[col0], b1 = sBias[col0 + 1];
        float cs0 = 0.f, cs1 = 0.f;
#pragma unroll
        for (int mi = 0; mi < 4; mi++) {
            cs0 += fmaxf(acc[mi][ni][0] + b0, 0.f) + fmaxf(acc[mi][ni][2] + b0, 0.f);
            cs1 += fmaxf(acc[mi][ni][1] + b1, 0.f) + fmaxf(acc[mi][ni][3] + b1, 0.f);
        }
#pragma unroll
        for (int o = 4; o <= 16; o <<= 1) {
            cs0 += __shfl_xor_sync(0xffffffffu, cs0, o);
            cs1 += __shfl_xor_sync(0xffffffffu, cs1, o);
        }
        if (g == 0) {
            atomicAdd(&g_pooled[b*HID + col0],     cs0);
            atomicAdd(&g_pooled[b*HID + col0 + 1], cs1);
        }
    }
}

// ---------------- classifier + pooled reset ----------------
__global__ void k_cls(const float* __restrict__ cls_w, const float* __restrict__ cls_b,
                      float* __restrict__ out) {
    int tid = threadIdx.x;
    if (tid < B_SZ*NCLS) {
        int b = tid / NCLS, c = tid % NCLS;
        float acc = 0.f;
        const float* pp = g_pooled + b*HID;
        const float* w = cls_w + c*HID;
        for (int h = 0; h < HID; h++) acc += pp[h] * w[h];
        out[b*NCLS + c] = cls_b[c] + acc * (1.f/(float)SEQ);
    }
    __syncthreads();
    for (int i = tid; i < B_SZ*HID; i += 256) g_pooled[i] = 0.f;  // reset for replay
}

// ---------------- launch ----------------
extern "C" void kernel_launch(void* const* d_in, const int* in_sizes, int n_in,
                              void* d_out, int out_size) {
    const int*   tokens = (const int*)  d_in[0];
    const int*   ei     = (const int*)  d_in[2];
    const float* emb    = (const float*)d_in[3];
    const float* A_log  = (const float*)d_in[4];
    const float* B_w    = (const float*)d_in[5];
    const float* C_w    = (const float*)d_in[6];
    const float* Dskip  = (const float*)d_in[7];
    const float* ln_g   = (const float*)d_in[8];
    const float* ln_b   = (const float*)d_in[9];
    const float* Wmsg   = (const float*)d_in[10];
    const float* Wupd   = (const float*)d_in[11];
    const float* Wupd_b = (const float*)d_in[12];
    const float* cls_w  = (const float*)d_in[13];
    const float* cls_b  = (const float*)d_in[14];
    float* out = (float*)d_out;

    const int VBLK = (VOCAB + VROWS - 1) / VROWS;   // 786

    k_s1    <<<S1_VP0 + VBLK, 256>>>(A_log, Wupd, Wmsg, ei, emb, B_w);
    k_s2    <<<144, 256>>>(tokens);
    k_s3    <<<1536, 256>>>(ei);
    k_yln   <<<NROW/8, 256>>>(tokens, emb, C_w, Dskip, ln_g, ln_b);
    k_gather<<<NROW/8, 256>>>();
    k_gemm  <<<(NROW/128)*2, 256>>>(Wupd_b);
    k_cls   <<<1, 256>>>(cls_w, cls_b, out);
}